// round 2
// baseline (speedup 1.0000x reference)
#include <cuda_runtime.h>
#include <cuda_bf16.h>
#include <cstdint>

// out[B,256] = (x[B,128] @ W[256,128]^T + bias)^2
// Persistent mma.sync (bf16 3-term split) kernel. No tcgen05 (harness PTX
// target is plain sm_103, arch-accelerated features unavailable).

#define DDIM   128
#define ODIM   256
#define TILE_M 128
#define NTILES 1024          // 131072 / 128
#define GRID   148
#define LOOKA  6
#define SLICE_STRIDE 80      // bytes per x-slice row: 16 fp32 + 16B pad
#define SLICE_BYTES  (TILE_M * SLICE_STRIDE)   // 10240

// smem layout
#define SM_RING  0
#define SM_WH    (8 * SLICE_BYTES)       // 81920
#define SM_WL    (SM_WH + 65536)         // 147456
#define SM_BIAS  (SM_WL + 65536)         // 212992
#define SM_TOTAL (SM_BIAS + 1024)        // 214016

static __device__ __forceinline__ uint32_t smem_u32(const void* p) {
    uint32_t a;
    asm("{ .reg .u64 t; cvta.to.shared.u64 t, %1; cvt.u32.u64 %0, t; }" : "=r"(a) : "l"(p));
    return a;
}

static __device__ __forceinline__ void cp16(uint32_t dst, const void* src) {
    asm volatile("cp.async.cg.shared.global [%0], [%1], 16;" :: "r"(dst), "l"(src) : "memory");
}
static __device__ __forceinline__ void cp_commit() {
    asm volatile("cp.async.commit_group;" ::: "memory");
}
static __device__ __forceinline__ void cp_wait_looka() {
    asm volatile("cp.async.wait_group %0;" :: "n"(LOOKA) : "memory");
}

static __device__ __forceinline__ void lds64(float& x, float& y, uint32_t a) {
    asm volatile("ld.shared.v2.f32 {%0, %1}, [%2];" : "=f"(x), "=f"(y) : "r"(a));
}
static __device__ __forceinline__ uint32_t lds32(uint32_t a) {
    uint32_t v;
    asm volatile("ld.shared.b32 %0, [%1];" : "=r"(v) : "r"(a));
    return v;
}
static __device__ __forceinline__ void sts32(uint32_t a, uint32_t v) {
    asm volatile("st.shared.b32 [%0], %1;" :: "r"(a), "r"(v));
}

// fp32 pair -> packed bf16 hi + packed bf16 residual(lo)
static __device__ __forceinline__ void split2(float x, float y, uint32_t& h, uint32_t& l) {
    __nv_bfloat16 hx = __float2bfloat16(x);
    __nv_bfloat16 hy = __float2bfloat16(y);
    float rx = x - __bfloat162float(hx);
    float ry = y - __bfloat162float(hy);
    __nv_bfloat162 hp;
    hp.x = hx; hp.y = hy;
    h = *reinterpret_cast<uint32_t*>(&hp);
    asm("cvt.rn.bf16x2.f32 %0, %1, %2;" : "=r"(l) : "f"(ry), "f"(rx));   // low = rx
}

static __device__ __forceinline__ void mma_bf16(float* d, const uint32_t* a,
                                                uint32_t b0, uint32_t b1) {
    asm volatile(
        "mma.sync.aligned.m16n8k16.row.col.f32.bf16.bf16.f32 "
        "{%0,%1,%2,%3}, {%4,%5,%6,%7}, {%8,%9}, {%0,%1,%2,%3};"
        : "+f"(d[0]), "+f"(d[1]), "+f"(d[2]), "+f"(d[3])
        : "r"(a[0]), "r"(a[1]), "r"(a[2]), "r"(a[3]), "r"(b0), "r"(b1));
}

// issue cp.async for x-slice j (tile j>>3, kstep j&7) into ring slot j&7
static __device__ __forceinline__ void issue_slice(int j, int bid, const float* xg,
                                                   uint32_t sb, int tid) {
    const int tile = bid + (j >> 3) * GRID;
    if (tile >= NTILES) return;
    const int ks = j & 7;
    const uint32_t dstb = sb + SM_RING + (uint32_t)(j & 7) * SLICE_BYTES;
    const size_t m0 = (size_t)tile * TILE_M;
    #pragma unroll
    for (int t = 0; t < 2; t++) {
        const int c   = tid + t * 256;        // 0..511
        const int row = c >> 2;
        const int ch  = c & 3;
        const float* src = xg + (m0 + row) * DDIM + ks * 16 + ch * 4;
        cp16(dstb + (uint32_t)row * SLICE_STRIDE + ch * 16, src);
    }
}

__global__ void __launch_bounds__(256, 1)
hyper_kernel(const float* __restrict__ xg, const float* __restrict__ wg,
             const float* __restrict__ bg, float* __restrict__ out) {
    extern __shared__ __align__(16) char smem[];
    const uint32_t sb = smem_u32(smem);
    const int tid  = threadIdx.x;
    const int lane = tid & 31;
    const int wid  = tid >> 5;
    const int wm   = wid >> 1;     // 0..3 : m-rows wm*32..+31
    const int wn   = wid & 1;      // 0..1 : n-cols wn*128..+127
    const int bid  = blockIdx.x;

    // ---- prologue: bias + W (fp32 -> bf16 hi/lo, XOR-swizzled) into smem ----
    reinterpret_cast<float*>(smem + SM_BIAS)[tid] = bg[tid];

    for (int i = tid; i < ODIM * 64; i += 256) {     // 64 words (2 bf16) per W row
        const int n  = i >> 6;
        const int kw = i & 63;
        float2 w = *reinterpret_cast<const float2*>(wg + n * DDIM + kw * 2);
        uint32_t h, l;
        split2(w.x, w.y, h, l);
        const uint32_t phys = (uint32_t)(n * 64 + (kw ^ ((n & 7) << 2))) << 2;
        sts32(sb + SM_WH + phys, h);
        sts32(sb + SM_WL + phys, l);
    }

    const int my_ntiles = (NTILES - bid + GRID - 1) / GRID;
    const int total = my_ntiles * 8;

    // prefetch pipeline prologue
    for (int j = 0; j < LOOKA; j++) {
        if (j < total) issue_slice(j, bid, xg, sb, tid);
        cp_commit();
    }

    // ---- accumulators: [mt][nt][4], bias-initialized ----
    float acc[2][16][4];
    const float* bs = reinterpret_cast<const float*>(smem + SM_BIAS);
    {
        // bias not yet sync'ed across threads, but each thread wrote bg[tid];
        // we need other threads' values -> read from global instead for init #0
        #pragma unroll
        for (int nt = 0; nt < 16; nt++) {
            const int cc = wn * 128 + nt * 8 + (lane & 3) * 2;
            float2 bv = *reinterpret_cast<const float2*>(bg + cc);
            #pragma unroll
            for (int mt = 0; mt < 2; mt++) {
                acc[mt][nt][0] = bv.x; acc[mt][nt][1] = bv.y;
                acc[mt][nt][2] = bv.x; acc[mt][nt][3] = bv.y;
            }
        }
    }

    const int r0c = wm * 32 + (lane >> 2);           // A-frag base row in tile
    const uint32_t acol = (uint32_t)(lane & 3) * 8;  // A-frag byte col in slice

    for (int j = 0; j < total; j++) {
        if (j + LOOKA < total) issue_slice(j + LOOKA, bid, xg, sb, tid);
        cp_commit();
        cp_wait_looka();
        __syncthreads();   // slice j visible to all; also orders W/bias stores (1st iter)

        const int ks = j & 7;
        const uint32_t slice = sb + SM_RING + (uint32_t)(j & 7) * SLICE_BYTES;

        // A fragments (fp32 from slice -> bf16 hi/lo packed)
        uint32_t ah[2][4], al[2][4];
        #pragma unroll
        for (int mt = 0; mt < 2; mt++) {
            const uint32_t ad = slice + (uint32_t)(r0c + mt * 16) * SLICE_STRIDE + acol;
            float f0x, f0y, f1x, f1y, f2x, f2y, f3x, f3y;
            lds64(f0x, f0y, ad);
            lds64(f1x, f1y, ad + 8 * SLICE_STRIDE);
            lds64(f2x, f2y, ad + 32);
            lds64(f3x, f3y, ad + 8 * SLICE_STRIDE + 32);
            split2(f0x, f0y, ah[mt][0], al[mt][0]);
            split2(f1x, f1y, ah[mt][1], al[mt][1]);
            split2(f2x, f2y, ah[mt][2], al[mt][2]);
            split2(f3x, f3y, ah[mt][3], al[mt][3]);
        }

        // B fragments from swizzled W smem + 3-term MMA
        const uint32_t kw0 = (uint32_t)(ks * 8) + (lane & 3);
        const uint32_t szr = ((uint32_t)(lane >> 2)) << 2;   // n&7 == lane>>2
        #pragma unroll
        for (int nt = 0; nt < 16; nt++) {
            const uint32_t nrow = (uint32_t)(wn * 128 + nt * 8 + (lane >> 2));
            const uint32_t o0 = (nrow * 64 + (kw0 ^ szr)) << 2;
            const uint32_t o1 = (nrow * 64 + ((kw0 + 4) ^ szr)) << 2;
            const uint32_t wh0 = lds32(sb + SM_WH + o0);
            const uint32_t wh1 = lds32(sb + SM_WH + o1);
            const uint32_t wl0 = lds32(sb + SM_WL + o0);
            const uint32_t wl1 = lds32(sb + SM_WL + o1);
            #pragma unroll
            for (int mt = 0; mt < 2; mt++) {
                mma_bf16(acc[mt][nt], ah[mt], wh0, wh1);   // xh*wh
                mma_bf16(acc[mt][nt], al[mt], wh0, wh1);   // xl*wh
                mma_bf16(acc[mt][nt], ah[mt], wl0, wl1);   // xh*wl
            }
        }

        if (ks == 7) {
            // epilogue: square + store, then bias-reinit accumulators
            const int tile = bid + (j >> 3) * GRID;
            const size_t m0 = (size_t)tile * TILE_M;
            #pragma unroll
            for (int mt = 0; mt < 2; mt++) {
                const size_t rr = m0 + (size_t)(wm * 32 + mt * 16 + (lane >> 2));
                #pragma unroll
                for (int nt = 0; nt < 16; nt++) {
                    const int cc = wn * 128 + nt * 8 + (lane & 3) * 2;
                    float2 s0, s1;
                    s0.x = acc[mt][nt][0] * acc[mt][nt][0];
                    s0.y = acc[mt][nt][1] * acc[mt][nt][1];
                    s1.x = acc[mt][nt][2] * acc[mt][nt][2];
                    s1.y = acc[mt][nt][3] * acc[mt][nt][3];
                    *reinterpret_cast<float2*>(out + rr * ODIM + cc) = s0;
                    *reinterpret_cast<float2*>(out + (rr + 8) * ODIM + cc) = s1;
                    float2 bv = *reinterpret_cast<const float2*>(bs + cc);
                    acc[mt][nt][0] = bv.x; acc[mt][nt][1] = bv.y;
                    acc[mt][nt][2] = bv.x; acc[mt][nt][3] = bv.y;
                }
            }
        }
    }
}

extern "C" void kernel_launch(void* const* d_in, const int* in_sizes, int n_in,
                              void* d_out, int out_size) {
    const float* x = (const float*)d_in[0];
    const float* w = (const float*)d_in[1];
    const float* b = (const float*)d_in[2];
    float* out = (float*)d_out;

    cudaFuncSetAttribute(hyper_kernel, cudaFuncAttributeMaxDynamicSharedMemorySize, SM_TOTAL);
    hyper_kernel<<<GRID, 256, SM_TOTAL>>>(x, w, b, out);
}

// round 3
// speedup vs baseline: 1.4676x; 1.4676x over previous
#include <cuda_runtime.h>
#include <cuda_fp16.h>
#include <cstdint>

// out[B,256] = (x[B,128] @ W[256,128]^T + bias)^2
// Persistent mma.sync fp16 2-term split: x = xh + xl (fp16), w single fp16.
// z = xh*w + xl*w (fp32 accum) -> error only from w rounding (~1.4e-4 rel).

#define DDIM   128
#define ODIM   256
#define TILE_M 128
#define NTILES 1024
#define GRID   148

// smem layout (bytes)
#define SM_W     0            // W fp16 [256][128], 256B/row swizzled -> 65536
#define SM_X     65536        // two x buffers, each: hi 32768 + lo 32768
#define XBUF_SZ  65536
#define XLO_OFF  32768
#define SM_BIAS  (SM_X + 2 * XBUF_SZ)   // 196608
#define SM_TOTAL (SM_BIAS + 1024)       // 197632

static __device__ __forceinline__ uint32_t smem_u32(const void* p) {
    uint32_t a;
    asm("{ .reg .u64 t; cvta.to.shared.u64 t, %1; cvt.u32.u64 %0, t; }" : "=r"(a) : "l"(p));
    return a;
}

static __device__ __forceinline__ void ldsm4(uint32_t* r, uint32_t a) {
    asm volatile("ldmatrix.sync.aligned.m8n8.x4.shared.b16 {%0,%1,%2,%3}, [%4];"
                 : "=r"(r[0]), "=r"(r[1]), "=r"(r[2]), "=r"(r[3]) : "r"(a));
}

static __device__ __forceinline__ void sts64(uint32_t a, uint32_t v0, uint32_t v1) {
    asm volatile("st.shared.v2.b32 [%0], {%1, %2};" :: "r"(a), "r"(v0), "r"(v1));
}

static __device__ __forceinline__ void mma_f16(float* d, const uint32_t* a,
                                               uint32_t b0, uint32_t b1) {
    asm volatile(
        "mma.sync.aligned.m16n8k16.row.col.f32.f16.f16.f32 "
        "{%0,%1,%2,%3}, {%4,%5,%6,%7}, {%8,%9}, {%0,%1,%2,%3};"
        : "+f"(d[0]), "+f"(d[1]), "+f"(d[2]), "+f"(d[3])
        : "r"(a[0]), "r"(a[1]), "r"(a[2]), "r"(a[3]), "r"(b0), "r"(b1));
}

// fp32 pair -> packed fp16 hi pair + packed fp16 residual pair
static __device__ __forceinline__ void splitf16(float x, float y, uint32_t& h, uint32_t& l) {
    __half hx = __float2half_rn(x);
    __half hy = __float2half_rn(y);
    float rx = x - __half2float(hx);
    float ry = y - __half2float(hy);
    __half2 hp; hp.x = hx; hp.y = hy;
    h = *reinterpret_cast<uint32_t*>(&hp);
    __half2 lp; lp.x = __float2half_rn(rx); lp.y = __float2half_rn(ry);
    l = *reinterpret_cast<uint32_t*>(&lp);
}

// convert one staged float4 (flat float4-index idx4 of a 128x128 tile) and STS
// into x buffer xb (hi at +0, lo at +XLO_OFF), XOR-swizzled 16B granules.
static __device__ __forceinline__ void cvt_sts_x(uint32_t xb, int idx4, float4 v) {
    const int row = idx4 >> 5;
    const int cg  = idx4 & 31;
    uint32_t h0, l0, h1, l1;
    splitf16(v.x, v.y, h0, l0);
    splitf16(v.z, v.w, h1, l1);
    const uint32_t a = xb + (uint32_t)row * 256 +
                       ((uint32_t)(((cg >> 1) ^ (row & 7)) << 4)) + ((cg & 1) << 3);
    sts64(a, h0, h1);
    sts64(a + XLO_OFF, l0, l1);
}

__global__ void __launch_bounds__(256, 1)
hyper_kernel(const float* __restrict__ xg, const float* __restrict__ wg,
             const float* __restrict__ bg, float* __restrict__ out) {
    extern __shared__ __align__(16) char smem[];
    const uint32_t sb = smem_u32(smem);
    const int tid  = threadIdx.x;
    const int lane = tid & 31;
    const int wid  = tid >> 5;
    const int wm   = wid >> 1;           // 0..3 : rows wm*32 .. +31
    const int wn   = wid & 1;            // 0..1 : cols wn*128 .. +127
    const int bid  = blockIdx.x;

    // ---- bias -> smem ----
    reinterpret_cast<float*>(smem + SM_BIAS)[tid] = bg[tid];

    // ---- W: fp32 -> fp16 (single term), swizzled smem [n][k], 256B rows ----
    {
        const float4* w4 = reinterpret_cast<const float4*>(wg);
        #pragma unroll 4
        for (int i = tid; i < ODIM * 32; i += 256) {
            const int n  = i >> 5;
            const int cg = i & 31;
            float4 v = w4[i];
            __half2 p0, p1;
            p0.x = __float2half_rn(v.x); p0.y = __float2half_rn(v.y);
            p1.x = __float2half_rn(v.z); p1.y = __float2half_rn(v.w);
            const uint32_t a = sb + SM_W + (uint32_t)n * 256 +
                               ((uint32_t)(((cg >> 1) ^ (n & 7)) << 4)) + ((cg & 1) << 3);
            sts64(a, *reinterpret_cast<uint32_t*>(&p0), *reinterpret_cast<uint32_t*>(&p1));
        }
    }

    // ---- accumulators [mt][nt][4], bias-initialized from global ----
    float acc[2][16][4];
    #pragma unroll
    for (int nt = 0; nt < 16; nt++) {
        const int cc = wn * 128 + nt * 8 + (lane & 3) * 2;
        float2 bv = *reinterpret_cast<const float2*>(bg + cc);
        #pragma unroll
        for (int mt = 0; mt < 2; mt++) {
            acc[mt][nt][0] = bv.x; acc[mt][nt][1] = bv.y;
            acc[mt][nt][2] = bv.x; acc[mt][nt][3] = bv.y;
        }
    }

    // ---- ldmatrix lane-address precompute ----
    const uint32_t lx  = (uint32_t)(lane & 7);
    const uint32_t khA = (uint32_t)((lane >> 4) & 1);     // A: k-half from lane/16
    const uint32_t khB = (uint32_t)((lane >> 3) & 1);     // B: k-half from lane/8
    const uint32_t arow_off = (uint32_t)(wm * 32 + (lane & 7) + ((lane & 8) ? 8 : 0)) * 256;
    const uint32_t preB0 = sb + SM_W +
                           (uint32_t)(wn * 128 + (lane & 7) + ((lane & 16) ? 8 : 0)) * 256;

    const int my_n = (NTILES - bid + GRID - 1) / GRID;
    const float4* xg4 = reinterpret_cast<const float4*>(xg);
    const float* bs = reinterpret_cast<const float*>(smem + SM_BIAS);

    // ---- prologue: fill x buffer 0 with tile 0 ----
    {
        const size_t b4 = (size_t)bid * TILE_M * 32;     // float4 base of tile
        #pragma unroll 4
        for (int it = 0; it < 16; it++) {
            const int idx4 = tid + it * 256;
            cvt_sts_x(sb + SM_X, idx4, xg4[b4 + idx4]);
        }
    }
    __syncthreads();

    for (int tt = 0; tt < my_n; tt++) {
        const int tile = bid + tt * GRID;
        const uint32_t xb  = sb + SM_X + (uint32_t)(tt & 1) * XBUF_SZ;
        const uint32_t nxb = sb + SM_X + (uint32_t)((tt + 1) & 1) * XBUF_SZ;
        const bool more = (tt + 1 < my_n);
        const size_t nb4 = more ? ((size_t)(tile + GRID) * TILE_M * 32) : 0;

        float4 stage[8];
        if (more) {
            #pragma unroll
            for (int it = 0; it < 8; it++) stage[it] = xg4[nb4 + tid + it * 256];
        }

        // ---- ks 0..3 ----
        #pragma unroll
        for (int ks = 0; ks < 4; ks++) {
            const uint32_t swA = ((((uint32_t)ks << 1) | khA) ^ lx) << 4;
            const uint32_t swB = ((((uint32_t)ks << 1) | khB) ^ lx) << 4;
            uint32_t ah[2][4], al[2][4];
            ldsm4(ah[0], xb + arow_off + swA);
            ldsm4(ah[1], xb + arow_off + 4096 + swA);
            ldsm4(al[0], xb + XLO_OFF + arow_off + swA);
            ldsm4(al[1], xb + XLO_OFF + arow_off + 4096 + swA);
            #pragma unroll
            for (int np = 0; np < 8; np++) {
                uint32_t bf[4];
                ldsm4(bf, preB0 + ((uint32_t)np << 12) + swB);
                #pragma unroll
                for (int mt = 0; mt < 2; mt++) {
                    mma_f16(acc[mt][2 * np],     ah[mt], bf[0], bf[1]);
                    mma_f16(acc[mt][2 * np],     al[mt], bf[0], bf[1]);
                    mma_f16(acc[mt][2 * np + 1], ah[mt], bf[2], bf[3]);
                    mma_f16(acc[mt][2 * np + 1], al[mt], bf[2], bf[3]);
                }
            }
        }

        if (more) {
            #pragma unroll
            for (int it = 0; it < 8; it++) cvt_sts_x(nxb, tid + it * 256, stage[it]);
            #pragma unroll
            for (int it = 0; it < 8; it++) stage[it] = xg4[nb4 + 2048 + tid + it * 256];
        }

        // ---- ks 4..7 ----
        #pragma unroll
        for (int ks = 4; ks < 8; ks++) {
            const uint32_t swA = ((((uint32_t)ks << 1) | khA) ^ lx) << 4;
            const uint32_t swB = ((((uint32_t)ks << 1) | khB) ^ lx) << 4;
            uint32_t ah[2][4], al[2][4];
            ldsm4(ah[0], xb + arow_off + swA);
            ldsm4(ah[1], xb + arow_off + 4096 + swA);
            ldsm4(al[0], xb + XLO_OFF + arow_off + swA);
            ldsm4(al[1], xb + XLO_OFF + arow_off + 4096 + swA);
            #pragma unroll
            for (int np = 0; np < 8; np++) {
                uint32_t bf[4];
                ldsm4(bf, preB0 + ((uint32_t)np << 12) + swB);
                #pragma unroll
                for (int mt = 0; mt < 2; mt++) {
                    mma_f16(acc[mt][2 * np],     ah[mt], bf[0], bf[1]);
                    mma_f16(acc[mt][2 * np],     al[mt], bf[0], bf[1]);
                    mma_f16(acc[mt][2 * np + 1], ah[mt], bf[2], bf[3]);
                    mma_f16(acc[mt][2 * np + 1], al[mt], bf[2], bf[3]);
                }
            }
        }

        if (more) {
            #pragma unroll
            for (int it = 0; it < 8; it++) cvt_sts_x(nxb, 2048 + tid + it * 256, stage[it]);
        }

        // ---- epilogue: square, store, bias-reinit ----
        {
            const size_t m0 = (size_t)tile * TILE_M;
            #pragma unroll
            for (int mt = 0; mt < 2; mt++) {
                const size_t rr = m0 + (size_t)(wm * 32 + mt * 16 + (lane >> 2));
                #pragma unroll
                for (int nt = 0; nt < 16; nt++) {
                    const int cc = wn * 128 + nt * 8 + (lane & 3) * 2;
                    float2 s0, s1;
                    s0.x = acc[mt][nt][0] * acc[mt][nt][0];
                    s0.y = acc[mt][nt][1] * acc[mt][nt][1];
                    s1.x = acc[mt][nt][2] * acc[mt][nt][2];
                    s1.y = acc[mt][nt][3] * acc[mt][nt][3];
                    *reinterpret_cast<float2*>(out + rr * ODIM + cc) = s0;
                    *reinterpret_cast<float2*>(out + (rr + 8) * ODIM + cc) = s1;
                    float2 bv = *reinterpret_cast<const float2*>(bs + cc);
                    acc[mt][nt][0] = bv.x; acc[mt][nt][1] = bv.y;
                    acc[mt][nt][2] = bv.x; acc[mt][nt][3] = bv.y;
                }
            }
        }

        __syncthreads();
    }
}

extern "C" void kernel_launch(void* const* d_in, const int* in_sizes, int n_in,
                              void* d_out, int out_size) {
    const float* x = (const float*)d_in[0];
    const float* w = (const float*)d_in[1];
    const float* b = (const float*)d_in[2];
    float* out = (float*)d_out;

    cudaFuncSetAttribute(hyper_kernel, cudaFuncAttributeMaxDynamicSharedMemorySize, SM_TOTAL);
    hyper_kernel<<<GRID, 256, SM_TOTAL>>>(x, w, b, out);
}